// round 1
// baseline (speedup 1.0000x reference)
#include <cuda_runtime.h>
#include <math_constants.h>

#define BS 8
#define NQ 1000
#define D 256
#define NROWS (BS * NQ)
#define TOPK 10
#define MAX_PAIRS (NROWS * TOPK)
#define RPB 16   // rows per block in batched GEMV kernels

// ---------------- scratch (no allocations allowed) ----------------
__device__ float g_id[NROWS * D];     // id_token
__device__ float g_cur[NROWS * D];    // running max of masked features
__device__ int   g_pairs[MAX_PAIRS * 2];
__device__ int   g_pair_count;
__device__ int   g_selcnt[NROWS];

__global__ void k_reset() { g_pair_count = 0; }

__device__ __forceinline__ void atomicMaxFloat(float* addr, float v) {
    if (v >= 0.0f) atomicMax((int*)addr, __float_as_int(v));
    else           atomicMin((unsigned int*)addr, __float_as_uint(v));
}

// ---------------- K2: IoU mask + candidate selection ----------------
// One block per (b,i) row. Writes attn_mask (as 0/1 float) and collects
// candidates j with overlap >= 0.5 (== iou>=0.5 && seed[j] && !seed[i]).
// Selects top-10 by value (tie -> smaller j) exactly as stable argsort would.
__global__ __launch_bounds__(256) void k_mask_sel(
    const float* __restrict__ pred, const float* __restrict__ seed,
    float* __restrict__ out_mask)
{
    const int row = blockIdx.x;
    const int b = row / NQ;

    __shared__ int   s_cnt;
    __shared__ float sval[256];
    __shared__ int   sidx[256];
    if (threadIdx.x == 0) s_cnt = 0;
    __syncthreads();

    const float4 pb = ((const float4*)pred)[row];
    const float bx1 = pb.x - 0.5f * pb.z, by1 = pb.y - 0.5f * pb.w;
    const float bx2 = pb.x + 0.5f * pb.z, by2 = pb.y + 0.5f * pb.w;
    const float ai  = (bx2 - bx1) * (by2 - by1);
    const bool negi = (seed[row] == 0.0f);

    for (int j = threadIdx.x; j < NQ; j += blockDim.x) {
        const float4 q = ((const float4*)pred)[b * NQ + j];
        const float qx1 = q.x - 0.5f * q.z, qy1 = q.y - 0.5f * q.w;
        const float qx2 = q.x + 0.5f * q.z, qy2 = q.y + 0.5f * q.w;
        const float aj  = (qx2 - qx1) * (qy2 - qy1);
        const float ltx = fmaxf(bx1, qx1), lty = fmaxf(by1, qy1);
        const float rbx = fminf(bx2, qx2), rby = fminf(by2, qy2);
        const float w = fmaxf(__fsub_rn(rbx, ltx), 0.0f);
        const float h = fmaxf(__fsub_rn(rby, lty), 0.0f);
        const float inter = __fmul_rn(w, h);
        const float uni = __fsub_rn(__fadd_rn(ai, aj), inter);
        const float iou = __fdiv_rn(inter, uni);
        const bool attn = (iou >= 0.5f);
        out_mask[row * NQ + j] = attn ? 1.0f : 0.0f;
        if (attn && negi && (seed[b * NQ + j] != 0.0f)) {
            int p = atomicAdd(&s_cnt, 1);
            if (p < 256) { sval[p] = iou; sidx[p] = j; }
        }
    }
    __syncthreads();

    if (threadIdx.x == 0) {
        int cnt = min(s_cnt, 256);
        int m;
        int sel[TOPK];
        if (cnt <= TOPK) {
            m = cnt;
            for (int t = 0; t < cnt; t++) sel[t] = sidx[t];
        } else {
            m = TOPK;
            for (int r = 0; r < TOPK; r++) {
                float best = -1.0f; int bj = 0x7fffffff; int bp = -1;
                for (int p = 0; p < cnt; p++) {
                    float v = sval[p]; int j = sidx[p];
                    if (v > best || (v == best && j < bj)) { best = v; bj = j; bp = p; }
                }
                sel[r] = bj;
                sval[bp] = -1.0f;
            }
        }
        g_selcnt[row] = m;
        if (m > 0) {
            int base = atomicAdd(&g_pair_count, m);
            for (int t = 0; t < m; t++) {
                g_pairs[2 * (base + t)]     = row;
                g_pairs[2 * (base + t) + 1] = sel[t];
            }
        }
    }
}

// ---------------- K3: id_token = LN(relu(tgt@W1+b1)@W2+b2) ----------------
// 16 rows per block, 256 threads; thread t owns output column t for 16 rows.
__global__ __launch_bounds__(256) void k_idtoken(
    const float* __restrict__ tgt,
    const float* __restrict__ W1, const float* __restrict__ b1,
    const float* __restrict__ W2, const float* __restrict__ b2,
    const float* __restrict__ g2, const float* __restrict__ be2)
{
    const int r0 = blockIdx.x * RPB;
    const int t = threadIdx.x;
    __shared__ float Ts[RPB][D];
    __shared__ float Hs[RPB][D];
    __shared__ float s_mean[RPB], s_rstd[RPB];

    for (int e = t; e < RPB * D; e += 256)
        Ts[e >> 8][e & 255] = tgt[r0 * D + e];
    __syncthreads();

    float acc[RPB];
#pragma unroll
    for (int r = 0; r < RPB; r++) acc[r] = b1[t];
    for (int k = 0; k < D; k++) {
        const float w = W1[k * D + t];
#pragma unroll
        for (int r = 0; r < RPB; r++) acc[r] = fmaf(Ts[r][k], w, acc[r]);
    }
#pragma unroll
    for (int r = 0; r < RPB; r++) Hs[r][t] = fmaxf(acc[r], 0.0f);
    __syncthreads();

#pragma unroll
    for (int r = 0; r < RPB; r++) acc[r] = b2[t];
    for (int k = 0; k < D; k++) {
        const float w = W2[k * D + t];
#pragma unroll
        for (int r = 0; r < RPB; r++) acc[r] = fmaf(Hs[r][k], w, acc[r]);
    }
#pragma unroll
    for (int r = 0; r < RPB; r++) Ts[r][t] = acc[r];
    __syncthreads();

    // per-row mean/var reduction: 8 warps, 2 rows each
    const int wid = t >> 5, lid = t & 31;
    for (int rr = wid; rr < RPB; rr += 8) {
        float s = 0.0f, sq = 0.0f;
        for (int c = lid; c < D; c += 32) { float v = Ts[rr][c]; s += v; sq += v * v; }
#pragma unroll
        for (int off = 16; off > 0; off >>= 1) {
            s  += __shfl_down_sync(0xffffffff, s,  off);
            sq += __shfl_down_sync(0xffffffff, sq, off);
        }
        if (lid == 0) {
            float m = s * (1.0f / D);
            s_mean[rr] = m;
            s_rstd[rr] = rsqrtf(sq * (1.0f / D) - m * m + 1e-5f);
        }
    }
    __syncthreads();

    const float gg = g2[t], bb = be2[t];
#pragma unroll
    for (int r = 0; r < RPB; r++)
        g_id[(r0 + r) * D + t] = (acc[r] - s_mean[r]) * s_rstd[r] * gg + bb;
}

// ---------------- K_init: cur = (m < 10) ? 0 : -inf ----------------
__global__ __launch_bounds__(256) void k_init() {
    const int idx = blockIdx.x * 256 + threadIdx.x;
    const int row = idx >> 8;
    g_cur[idx] = (g_selcnt[row] < TOPK) ? 0.0f : -CUDART_INF_F;
}

// ---------------- K4a: sparse neighbor MLP + atomic max ----------------
// 16 pairs per block; pair (row, j): f = relu((id_row - id_j)@W3+b3)@W4+b4
__global__ __launch_bounds__(256) void k_feat(
    const float* __restrict__ W3, const float* __restrict__ b3,
    const float* __restrict__ W4, const float* __restrict__ b4)
{
    const int g0 = blockIdx.x * RPB;
    const int npairs = g_pair_count;
    if (g0 >= npairs) return;
    const int t = threadIdx.x;
    const int ng = min(RPB, npairs - g0);

    __shared__ float Ds[RPB][D];
    __shared__ float Hs[RPB][D];
    __shared__ int   srow[RPB];

    for (int e = t; e < RPB * D; e += 256) {
        const int p = e >> 8, c = e & 255;
        if (p < ng) {
            const int row = g_pairs[2 * (g0 + p)];
            const int j   = g_pairs[2 * (g0 + p) + 1];
            const int b   = row / NQ;
            Ds[p][c] = g_id[row * D + c] - g_id[(b * NQ + j) * D + c];
            if (c == 0) srow[p] = row;
        } else {
            Ds[p][c] = 0.0f;
        }
    }
    __syncthreads();

    float acc[RPB];
#pragma unroll
    for (int r = 0; r < RPB; r++) acc[r] = b3[t];
    for (int k = 0; k < D; k++) {
        const float w = W3[k * D + t];
#pragma unroll
        for (int r = 0; r < RPB; r++) acc[r] = fmaf(Ds[r][k], w, acc[r]);
    }
#pragma unroll
    for (int r = 0; r < RPB; r++) Hs[r][t] = fmaxf(acc[r], 0.0f);
    __syncthreads();

#pragma unroll
    for (int r = 0; r < RPB; r++) acc[r] = b4[t];
    for (int k = 0; k < D; k++) {
        const float w = W4[k * D + t];
#pragma unroll
        for (int r = 0; r < RPB; r++) acc[r] = fmaf(Hs[r][k], w, acc[r]);
    }
    for (int r = 0; r < ng; r++)
        atomicMaxFloat(&g_cur[srow[r] * D + t], acc[r]);
}

// ---------------- K4b: out = tgt + relu(cur@W5+b5) * neg ----------------
__global__ __launch_bounds__(256) void k_out(
    const float* __restrict__ tgt, const float* __restrict__ seed,
    const float* __restrict__ W5, const float* __restrict__ b5,
    float* __restrict__ out)
{
    const int r0 = blockIdx.x * RPB;
    const int t = threadIdx.x;
    __shared__ float Cs[RPB][D];
    __shared__ float s_neg[RPB];

    for (int e = t; e < RPB * D; e += 256)
        Cs[e >> 8][e & 255] = g_cur[r0 * D + e];
    if (t < RPB) s_neg[t] = 1.0f - seed[r0 + t];
    __syncthreads();

    float acc[RPB];
#pragma unroll
    for (int r = 0; r < RPB; r++) acc[r] = b5[t];
    for (int k = 0; k < D; k++) {
        const float w = W5[k * D + t];
#pragma unroll
        for (int r = 0; r < RPB; r++) acc[r] = fmaf(Cs[r][k], w, acc[r]);
    }
#pragma unroll
    for (int r = 0; r < RPB; r++) {
        const int row = r0 + r;
        out[row * D + t] = tgt[row * D + t] + fmaxf(acc[r], 0.0f) * s_neg[r];
    }
}

// ---------------- launch ----------------
extern "C" void kernel_launch(void* const* d_in, const int* in_sizes, int n_in,
                              void* d_out, int out_size) {
    const float* tgt  = (const float*)d_in[0];
    const float* seed = (const float*)d_in[1];
    const float* pred = (const float*)d_in[2];
    const float* W1 = (const float*)d_in[3];  const float* b1 = (const float*)d_in[4];
    const float* W2 = (const float*)d_in[5];  const float* b2 = (const float*)d_in[6];
    const float* g2 = (const float*)d_in[7];  const float* be2 = (const float*)d_in[8];
    const float* W3 = (const float*)d_in[9];  const float* b3 = (const float*)d_in[10];
    const float* W4 = (const float*)d_in[11]; const float* b4 = (const float*)d_in[12];
    const float* W5 = (const float*)d_in[13]; const float* b5 = (const float*)d_in[14];

    float* out = (float*)d_out;                 // cur_tgt: 8*1000*256 floats
    float* out_mask = out + (size_t)NROWS * D;  // attn_mask: 8*1000*1000 floats (0/1)

    k_reset<<<1, 1>>>();
    k_mask_sel<<<NROWS, 256>>>(pred, seed, out_mask);
    k_idtoken<<<NROWS / RPB, 256>>>(tgt, W1, b1, W2, b2, g2, be2);
    k_init<<<NROWS, 256>>>();
    k_feat<<<MAX_PAIRS / RPB, 256>>>(W3, b3, W4, b4);
    k_out<<<NROWS / RPB, 256>>>(tgt, seed, W5, b5, out);
}

// round 2
// speedup vs baseline: 1.6188x; 1.6188x over previous
#include <cuda_runtime.h>
#include <math_constants.h>

#define BS 8
#define NQ 1000
#define D 256
#define NROWS (BS * NQ)
#define TOPK 10
#define MAX_PAIRS (NROWS * TOPK)
#define RPB 16    // rows per block in batched GEMV kernels
#define MROWS 4   // rows per block in mask kernel

// ---------------- scratch (no allocations allowed) ----------------
__device__ float g_id[NROWS * D];     // id_token (only active rows valid)
__device__ float g_cur[NROWS * D];    // running max of masked features
__device__ int   g_pairs[MAX_PAIRS * 2];
__device__ int   g_pair_count;
__device__ int   g_selcnt[NROWS];
__device__ int   g_flag[NROWS];       // row needs id_token
__device__ int   g_idrows[NROWS];
__device__ int   g_nid;
__device__ int   g_outrows[NROWS];
__device__ int   g_nout;

__global__ void k_reset() {
    const int i = blockIdx.x * 256 + threadIdx.x;
    if (i < NROWS) g_flag[i] = 0;
    if (i == 0) { g_pair_count = 0; g_nid = 0; g_nout = 0; }
}

__device__ __forceinline__ void atomicMaxFloat(float* addr, float v) {
    if (v >= 0.0f) atomicMax((int*)addr, __float_as_int(v));
    else           atomicMin((unsigned int*)addr, __float_as_uint(v));
}

// ---------------- K2: IoU mask + candidate selection + cur init ----------------
// 4 rows per block; boxes + seeds cached in shared. Selects top-10 by value
// (tie -> smaller j) exactly as stable argsort would; records pairs, flags,
// out-row list, and initializes g_cur for its rows.
__global__ __launch_bounds__(256) void k_mask_sel(
    const float* __restrict__ pred, const float* __restrict__ seed,
    float* __restrict__ out_mask)
{
    const int base = blockIdx.x * MROWS;
    const int b = base / NQ;            // all MROWS rows in same batch (1000 % 4 == 0)
    const int t = threadIdx.x;

    __shared__ float4 s_box[NQ];
    __shared__ float  s_seed[NQ];
    __shared__ int    s_cnt, s_m;
    __shared__ float  sval[256];
    __shared__ int    sidx[256];

    for (int j = t; j < NQ; j += 256) {
        s_box[j]  = ((const float4*)pred)[b * NQ + j];
        s_seed[j] = seed[b * NQ + j];
    }
    __syncthreads();

    for (int r = 0; r < MROWS; r++) {
        const int row = base + r;
        const int li  = row - b * NQ;
        if (t == 0) s_cnt = 0;
        __syncthreads();

        const float4 pb = s_box[li];
        const float bx1 = __fsub_rn(pb.x, __fmul_rn(0.5f, pb.z));
        const float by1 = __fsub_rn(pb.y, __fmul_rn(0.5f, pb.w));
        const float bx2 = __fadd_rn(pb.x, __fmul_rn(0.5f, pb.z));
        const float by2 = __fadd_rn(pb.y, __fmul_rn(0.5f, pb.w));
        const float ai  = __fmul_rn(__fsub_rn(bx2, bx1), __fsub_rn(by2, by1));
        const bool negi = (s_seed[li] == 0.0f);

        for (int j = t; j < NQ; j += 256) {
            const float4 q = s_box[j];
            const float qx1 = __fsub_rn(q.x, __fmul_rn(0.5f, q.z));
            const float qy1 = __fsub_rn(q.y, __fmul_rn(0.5f, q.w));
            const float qx2 = __fadd_rn(q.x, __fmul_rn(0.5f, q.z));
            const float qy2 = __fadd_rn(q.y, __fmul_rn(0.5f, q.w));
            const float aj  = __fmul_rn(__fsub_rn(qx2, qx1), __fsub_rn(qy2, qy1));
            const float w = fmaxf(__fsub_rn(fminf(bx2, qx2), fmaxf(bx1, qx1)), 0.0f);
            const float h = fmaxf(__fsub_rn(fminf(by2, qy2), fmaxf(by1, qy1)), 0.0f);
            const float inter = __fmul_rn(w, h);
            const float uni = __fsub_rn(__fadd_rn(ai, aj), inter);
            const float iou = __fdiv_rn(inter, uni);
            const bool attn = (iou >= 0.5f);
            out_mask[(size_t)row * NQ + j] = attn ? 1.0f : 0.0f;
            if (attn && negi && (s_seed[j] != 0.0f)) {
                int p = atomicAdd(&s_cnt, 1);
                if (p < 256) { sval[p] = iou; sidx[p] = j; }
            }
        }
        __syncthreads();

        if (t == 0) {
            int cnt = min(s_cnt, 256);
            int m;
            int sel[TOPK];
            if (cnt <= TOPK) {
                m = cnt;
                for (int q = 0; q < cnt; q++) sel[q] = sidx[q];
            } else {
                m = TOPK;
                for (int rr = 0; rr < TOPK; rr++) {
                    float best = -1.0f; int bj = 0x7fffffff; int bp = -1;
                    for (int p = 0; p < cnt; p++) {
                        float v = sval[p]; int j = sidx[p];
                        if (v > best || (v == best && j < bj)) { best = v; bj = j; bp = p; }
                    }
                    sel[rr] = bj;
                    sval[bp] = -1.0f;
                }
            }
            s_m = m;
            g_selcnt[row] = m;
            if (m > 0) {
                int pbase = atomicAdd(&g_pair_count, m);
                for (int q = 0; q < m; q++) {
                    g_pairs[2 * (pbase + q)]     = row;
                    g_pairs[2 * (pbase + q) + 1] = sel[q];
                    g_flag[b * NQ + sel[q]] = 1;
                }
                g_flag[row] = 1;
                int op = atomicAdd(&g_nout, 1);
                g_outrows[op] = row;
            }
        }
        __syncthreads();
        g_cur[(size_t)row * D + t] = (s_m < TOPK) ? 0.0f : -CUDART_INF_F;
    }
}

// ---------------- compaction of id-rows ----------------
__global__ void k_compact() {
    const int i = blockIdx.x * 256 + threadIdx.x;
    if (i < NROWS && g_flag[i]) {
        int p = atomicAdd(&g_nid, 1);
        g_idrows[p] = i;
    }
}

// ---------------- K3: id_token = LN(relu(tgt@W1+b1)@W2+b2), active rows ----------------
__global__ __launch_bounds__(256) void k_idtoken(
    const float* __restrict__ tgt,
    const float* __restrict__ W1, const float* __restrict__ b1,
    const float* __restrict__ W2, const float* __restrict__ b2,
    const float* __restrict__ g2, const float* __restrict__ be2)
{
    const int g0 = blockIdx.x * RPB;
    const int nact = g_nid;
    if (g0 >= nact) return;
    const int ng = min(RPB, nact - g0);
    const int t = threadIdx.x;

    __shared__ __align__(16) float Ts[RPB][D];
    __shared__ __align__(16) float Hs[RPB][D];
    __shared__ float s_mean[RPB], s_rstd[RPB];
    __shared__ int   srow[RPB];

    if (t < RPB) srow[t] = g_idrows[g0 + ((t < ng) ? t : 0)];
    __syncthreads();

    for (int e = t; e < RPB * (D / 4); e += 256) {
        const int p = e >> 6, c = e & 63;
        ((float4*)Ts[p])[c] = ((const float4*)(tgt + (size_t)srow[p] * D))[c];
    }
    __syncthreads();

    float acc[RPB];
#pragma unroll
    for (int r = 0; r < RPB; r++) acc[r] = b1[t];
    for (int k = 0; k < D; k += 4) {
        const float w0 = W1[(k + 0) * D + t];
        const float w1 = W1[(k + 1) * D + t];
        const float w2 = W1[(k + 2) * D + t];
        const float w3 = W1[(k + 3) * D + t];
#pragma unroll
        for (int r = 0; r < RPB; r++) {
            const float4 a = *((const float4*)&Ts[r][k]);
            acc[r] = fmaf(a.x, w0, acc[r]);
            acc[r] = fmaf(a.y, w1, acc[r]);
            acc[r] = fmaf(a.z, w2, acc[r]);
            acc[r] = fmaf(a.w, w3, acc[r]);
        }
    }
#pragma unroll
    for (int r = 0; r < RPB; r++) Hs[r][t] = fmaxf(acc[r], 0.0f);
    __syncthreads();

#pragma unroll
    for (int r = 0; r < RPB; r++) acc[r] = b2[t];
    for (int k = 0; k < D; k += 4) {
        const float w0 = W2[(k + 0) * D + t];
        const float w1 = W2[(k + 1) * D + t];
        const float w2 = W2[(k + 2) * D + t];
        const float w3 = W2[(k + 3) * D + t];
#pragma unroll
        for (int r = 0; r < RPB; r++) {
            const float4 a = *((const float4*)&Hs[r][k]);
            acc[r] = fmaf(a.x, w0, acc[r]);
            acc[r] = fmaf(a.y, w1, acc[r]);
            acc[r] = fmaf(a.z, w2, acc[r]);
            acc[r] = fmaf(a.w, w3, acc[r]);
        }
    }
#pragma unroll
    for (int r = 0; r < RPB; r++) Ts[r][t] = acc[r];
    __syncthreads();

    const int wid = t >> 5, lid = t & 31;
    for (int rr = wid; rr < RPB; rr += 8) {
        float s = 0.0f, sq = 0.0f;
        for (int c = lid; c < D; c += 32) { float v = Ts[rr][c]; s += v; sq += v * v; }
#pragma unroll
        for (int off = 16; off > 0; off >>= 1) {
            s  += __shfl_down_sync(0xffffffff, s,  off);
            sq += __shfl_down_sync(0xffffffff, sq, off);
        }
        if (lid == 0) {
            float m = s * (1.0f / D);
            s_mean[rr] = m;
            s_rstd[rr] = rsqrtf(sq * (1.0f / D) - m * m + 1e-5f);
        }
    }
    __syncthreads();

    const float gg = g2[t], bb = be2[t];
#pragma unroll
    for (int r = 0; r < RPB; r++)
        if (r < ng)
            g_id[(size_t)srow[r] * D + t] = (acc[r] - s_mean[r]) * s_rstd[r] * gg + bb;
}

// ---------------- K4a: sparse neighbor MLP + atomic max ----------------
__global__ __launch_bounds__(256) void k_feat(
    const float* __restrict__ W3, const float* __restrict__ b3,
    const float* __restrict__ W4, const float* __restrict__ b4)
{
    const int g0 = blockIdx.x * RPB;
    const int npairs = g_pair_count;
    if (g0 >= npairs) return;
    const int t = threadIdx.x;
    const int ng = min(RPB, npairs - g0);

    __shared__ __align__(16) float Ds[RPB][D];
    __shared__ __align__(16) float Hs[RPB][D];
    __shared__ int srow[RPB], sj[RPB];

    if (t < RPB) {
        if (t < ng) {
            srow[t] = g_pairs[2 * (g0 + t)];
            sj[t]   = g_pairs[2 * (g0 + t) + 1];
        } else {
            srow[t] = -1;
        }
    }
    __syncthreads();

    for (int e = t; e < RPB * (D / 4); e += 256) {
        const int p = e >> 6, c = e & 63;
        const int row = srow[p];
        if (row >= 0) {
            const int bb = row / NQ;
            const float4 a  = ((const float4*)(g_id + (size_t)row * D))[c];
            const float4 nb = ((const float4*)(g_id + (size_t)(bb * NQ + sj[p]) * D))[c];
            float4 dv;
            dv.x = a.x - nb.x; dv.y = a.y - nb.y; dv.z = a.z - nb.z; dv.w = a.w - nb.w;
            ((float4*)Ds[p])[c] = dv;
        } else {
            ((float4*)Ds[p])[c] = make_float4(0.f, 0.f, 0.f, 0.f);
        }
    }
    __syncthreads();

    float acc[RPB];
#pragma unroll
    for (int r = 0; r < RPB; r++) acc[r] = b3[t];
    for (int k = 0; k < D; k += 4) {
        const float w0 = W3[(k + 0) * D + t];
        const float w1 = W3[(k + 1) * D + t];
        const float w2 = W3[(k + 2) * D + t];
        const float w3 = W3[(k + 3) * D + t];
#pragma unroll
        for (int r = 0; r < RPB; r++) {
            const float4 a = *((const float4*)&Ds[r][k]);
            acc[r] = fmaf(a.x, w0, acc[r]);
            acc[r] = fmaf(a.y, w1, acc[r]);
            acc[r] = fmaf(a.z, w2, acc[r]);
            acc[r] = fmaf(a.w, w3, acc[r]);
        }
    }
#pragma unroll
    for (int r = 0; r < RPB; r++) Hs[r][t] = fmaxf(acc[r], 0.0f);
    __syncthreads();

#pragma unroll
    for (int r = 0; r < RPB; r++) acc[r] = b4[t];
    for (int k = 0; k < D; k += 4) {
        const float w0 = W4[(k + 0) * D + t];
        const float w1 = W4[(k + 1) * D + t];
        const float w2 = W4[(k + 2) * D + t];
        const float w3 = W4[(k + 3) * D + t];
#pragma unroll
        for (int r = 0; r < RPB; r++) {
            const float4 a = *((const float4*)&Hs[r][k]);
            acc[r] = fmaf(a.x, w0, acc[r]);
            acc[r] = fmaf(a.y, w1, acc[r]);
            acc[r] = fmaf(a.z, w2, acc[r]);
            acc[r] = fmaf(a.w, w3, acc[r]);
        }
    }
    for (int r = 0; r < ng; r++)
        atomicMaxFloat(&g_cur[(size_t)srow[r] * D + t], acc[r]);
}

// ---------------- K4b-base: rows with no valid candidates ----------------
// cur = 0  ->  out = tgt + relu(b5) * neg
__global__ __launch_bounds__(256) void k_out_base(
    const float* __restrict__ tgt, const float* __restrict__ seed,
    const float* __restrict__ b5, float* __restrict__ out)
{
    const int r0 = blockIdx.x * RPB;
    const int t = threadIdx.x;
    const float rb = fmaxf(b5[t], 0.0f);
#pragma unroll
    for (int r = 0; r < RPB; r++) {
        const int row = r0 + r;
        if (g_selcnt[row] == 0) {
            const float neg = 1.0f - seed[row];
            out[(size_t)row * D + t] = tgt[(size_t)row * D + t] + rb * neg;
        }
    }
}

// ---------------- K4b-gemv: active rows (m>0, neg==1) ----------------
__global__ __launch_bounds__(256) void k_out_gemv(
    const float* __restrict__ tgt,
    const float* __restrict__ W5, const float* __restrict__ b5,
    float* __restrict__ out)
{
    const int g0 = blockIdx.x * RPB;
    const int nact = g_nout;
    if (g0 >= nact) return;
    const int ng = min(RPB, nact - g0);
    const int t = threadIdx.x;

    __shared__ __align__(16) float Cs[RPB][D];
    __shared__ int srow[RPB];

    if (t < RPB) srow[t] = g_outrows[g0 + ((t < ng) ? t : 0)];
    __syncthreads();

    for (int e = t; e < RPB * (D / 4); e += 256) {
        const int p = e >> 6, c = e & 63;
        ((float4*)Cs[p])[c] = ((const float4*)(g_cur + (size_t)srow[p] * D))[c];
    }
    __syncthreads();

    float acc[RPB];
#pragma unroll
    for (int r = 0; r < RPB; r++) acc[r] = b5[t];
    for (int k = 0; k < D; k += 4) {
        const float w0 = W5[(k + 0) * D + t];
        const float w1 = W5[(k + 1) * D + t];
        const float w2 = W5[(k + 2) * D + t];
        const float w3 = W5[(k + 3) * D + t];
#pragma unroll
        for (int r = 0; r < RPB; r++) {
            const float4 a = *((const float4*)&Cs[r][k]);
            acc[r] = fmaf(a.x, w0, acc[r]);
            acc[r] = fmaf(a.y, w1, acc[r]);
            acc[r] = fmaf(a.z, w2, acc[r]);
            acc[r] = fmaf(a.w, w3, acc[r]);
        }
    }
#pragma unroll
    for (int r = 0; r < RPB; r++) {
        if (r < ng) {
            const int row = srow[r];
            out[(size_t)row * D + t] = tgt[(size_t)row * D + t] + fmaxf(acc[r], 0.0f);
        }
    }
}

// ---------------- launch ----------------
extern "C" void kernel_launch(void* const* d_in, const int* in_sizes, int n_in,
                              void* d_out, int out_size) {
    const float* tgt  = (const float*)d_in[0];
    const float* seed = (const float*)d_in[1];
    const float* pred = (const float*)d_in[2];
    const float* W1 = (const float*)d_in[3];  const float* b1 = (const float*)d_in[4];
    const float* W2 = (const float*)d_in[5];  const float* b2 = (const float*)d_in[6];
    const float* g2 = (const float*)d_in[7];  const float* be2 = (const float*)d_in[8];
    const float* W3 = (const float*)d_in[9];  const float* b3 = (const float*)d_in[10];
    const float* W4 = (const float*)d_in[11]; const float* b4 = (const float*)d_in[12];
    const float* W5 = (const float*)d_in[13]; const float* b5 = (const float*)d_in[14];

    float* out = (float*)d_out;                 // cur_tgt: 8*1000*256 floats
    float* out_mask = out + (size_t)NROWS * D;  // attn_mask: 8*1000*1000 floats (0/1)

    k_reset<<<(NROWS + 255) / 256, 256>>>();
    k_mask_sel<<<NROWS / MROWS, 256>>>(pred, seed, out_mask);
    k_compact<<<(NROWS + 255) / 256, 256>>>();
    k_idtoken<<<NROWS / RPB, 256>>>(tgt, W1, b1, W2, b2, g2, be2);
    k_feat<<<MAX_PAIRS / RPB, 256>>>(W3, b3, W4, b4);
    k_out_base<<<NROWS / RPB, 256>>>(tgt, seed, b5, out);
    k_out_gemv<<<NROWS / RPB, 256>>>(tgt, W5, b5, out);
}